// round 11
// baseline (speedup 1.0000x reference)
#include <cuda_runtime.h>
#include <math.h>

// Problem constants
#define LSC   2
#define BSC   16
#define NHC   256
#define NPARTC 512
#define MIDP  256
#define TTC   16
#define DINC  64
#define FHC   1024

// Output layout: tuple (W_mu(16,1), sig(16,1,1), pf(2,16,256,512), wf(16,512), l, nis)
#define OFF_WMU 0
#define OFF_SIG 16
#define OFF_PF  32
#define OFF_WF  (32 + LSC*BSC*NHC*NPARTC)
#define OFF_L   (OFF_WF + BSC*NPARTC)
#define OFF_NIS (OFF_L + 1)

// ---- tiny globals only (33 KB, identical to the proven R9 config) -----------
__device__ int g_idx[BSC*2*MIDP];
__device__ int g_do[BSC*2];

__device__ __forceinline__ float sigf(float x)   { return 1.0f/(1.0f+__expf(-x)); }
__device__ __forceinline__ float tanhfa(float x) { return 2.0f/(1.0f+__expf(-2.0f*x)) - 1.0f; }

__device__ __forceinline__ float bsum(float* red, int tid, int nthr, float v){
    red[tid]=v; __syncthreads();
    for (int s=nthr>>1; s>0; s>>=1){ if(tid<s) red[tid]+=red[tid+s]; __syncthreads(); }
    float r = red[0]; __syncthreads(); return r;
}
__device__ __forceinline__ float bmax(float* red, int tid, int nthr, float v){
    red[tid]=v; __syncthreads();
    for (int s=nthr>>1; s>0; s>>=1){ if(tid<s) red[tid]=fmaxf(red[tid],red[tid+s]); __syncthreads(); }
    float r = red[0]; __syncthreads(); return r;
}

// =============================================================================
// Persistent LSTM kernel: 128 CTAs x 256 threads. CTA = (batch b, particles
// p0..p0+31). All state in shared for all 16 steps. Double-buffered 8-k weight
// tiles (register prefetch), one __syncthreads per tile.
// Shared layout (floats):
//   [0)      Hb: 4 x [32][256]  (h0 p0/p1, h1 p0/p1)           32768
//   [32768)  C0: [32][256]                                      8192
//   [40960)  C1: [32][256]                                      8192
//   [49152)  WT0: [8][256]                                      2048
//   [51200)  WT1: [8][256]                                      2048
//   [53248)  XWV: [1024]                                        1024
//   [54272)  B1P: [1024]                                        1024
//   [55296)  XR:  [64]                                            64
//   total 55360 floats = 221440 bytes
// =============================================================================
#define SMEM_FLOATS 55360
#define SMEM_BYTES  (SMEM_FLOATS*4)

__global__ __launch_bounds__(256)
void k_lstm(const float* __restrict__ x, const float* __restrict__ particles,
            const float* __restrict__ q, const float* __restrict__ e,
            const float* __restrict__ Wih0, const float* __restrict__ Whh0,
            const float* __restrict__ b0,
            const float* __restrict__ Wih1, const float* __restrict__ Whh1,
            const float* __restrict__ b1,
            const float* __restrict__ eps_h, const float* __restrict__ eps_c,
            float* __restrict__ pf){
    extern __shared__ __align__(16) float sm[];
    float* Hb  = sm;
    float* C0  = sm + 32768;
    float* C1  = sm + 40960;
    float* WTb[2] = { sm + 49152, sm + 51200 };
    float* XWV = sm + 53248;
    float* B1P = sm + 54272;
    float* XR  = sm + 55296;

    int tid = threadIdx.x;
    int tx = tid & 63, ty = tid >> 6;      // ty: 8 rows each; tx: 1 unit (4 gate cols)
    int blk = blockIdx.x;
    int b = blk >> 3;
    int p0 = (blk & 7) * 32;

    // ---- init: load particle states ----
    for (int idx = tid; idx < 8192; idx += 256){
        int row = idx >> 8, u = idx & 255; int p = p0 + row;
        size_t base0 = ((size_t)(0*BSC + b)*NHC + u)*NPARTC;
        size_t base1 = ((size_t)(1*BSC + b)*NHC + u)*NPARTC;
        Hb[0*8192 + row*256 + u] = particles[base0 + p];
        Hb[2*8192 + row*256 + u] = particles[base1 + p];
        C0[row*256 + u] = particles[base0 + MIDP + p];
        C1[row*256 + u] = particles[base1 + MIDP + p];
    }
    for (int jp = tid; jp < 1024; jp += 256){
        int jo = ((jp & 3) << 8) | (jp >> 2);
        B1P[jp] = b1[jo];
    }
    __syncthreads();

    // ---- time loop ----
    for (int t = 0; t < TTC; t++){
        int cur = t & 1;
        float* h0c = Hb + cur*8192;
        float* h0n = Hb + (cur^1)*8192;
        float* h1c = Hb + (2+cur)*8192;
        float* h1n = Hb + (2+(cur^1))*8192;

        if (tid < 64) XR[tid] = x[(b*TTC + t)*DINC + tid];
        __syncthreads();
        for (int jp = tid; jp < 1024; jp += 256){
            int jo = ((jp & 3) << 8) | (jp >> 2);
            const float* wr = Wih0 + jo*DINC;
            float acc = b0[jo];
            #pragma unroll
            for (int k = 0; k < DINC; k++) acc = fmaf(XR[k], wr[k], acc);
            XWV[jp] = acc;
        }
        // XWV visibility covered by first in-chunk __syncthreads below

        for (int layer = 0; layer < 2; layer++){
            const float* Wa = (layer==0) ? Whh0 : Wih1;
            const float* Wb = Whh1;
            const float* Ain0 = (layer==0) ? h0c : h0n;
            const float* Ain1 = h1c;
            float* hout = (layer==0) ? h0n : h1n;
            float* cs   = (layer==0) ? C0 : C1;
            const float* pre = (layer==0) ? XWV : B1P;
            int nkt = (layer==0) ? 32 : 64;    // 8-k tiles

            for (int chunk = 0; chunk < 4; chunk++){
                int jp = chunk*256 + tid;
                int jo = ((jp & 3) << 8) | (jp >> 2);

                float4 acc4[8];
                #pragma unroll
                for (int i=0;i<8;i++) acc4[i] = make_float4(0.f,0.f,0.f,0.f);

                // prologue: load tile 0 into buffer 0
                {
                    const float* wr = Wa + (size_t)jo*256;
                    float4 w0 = *reinterpret_cast<const float4*>(wr);
                    float4 w1 = *reinterpret_cast<const float4*>(wr+4);
                    float* W = WTb[0];
                    W[0*256+tid]=w0.x; W[1*256+tid]=w0.y; W[2*256+tid]=w0.z; W[3*256+tid]=w0.w;
                    W[4*256+tid]=w1.x; W[5*256+tid]=w1.y; W[6*256+tid]=w1.z; W[7*256+tid]=w1.w;
                }
                __syncthreads();

                int bufc = 0;
                for (int kt = 0; kt < nkt; kt++){
                    // prefetch next tile into registers
                    float4 p0r = make_float4(0.f,0.f,0.f,0.f);
                    float4 p1r = make_float4(0.f,0.f,0.f,0.f);
                    int ktn = kt + 1;
                    if (ktn < nkt){
                        const float* Wsrc = (ktn >= 32) ? Wb : Wa;
                        int k0n = (ktn & 31) * 8;
                        const float* wr = Wsrc + (size_t)jo*256 + k0n;
                        p0r = *reinterpret_cast<const float4*>(wr);
                        p1r = *reinterpret_cast<const float4*>(wr+4);
                    }
                    // compute on current buffer
                    {
                        const float* Asrc = (kt >= 32) ? Ain1 : Ain0;
                        int klocal = (kt & 31) * 8;
                        const float* W = WTb[bufc];
                        #pragma unroll
                        for (int qq=0; qq<2; qq++){
                            float4 a[8];
                            #pragma unroll
                            for (int i=0;i<8;i++)
                                a[i] = *reinterpret_cast<const float4*>(
                                           &Asrc[(ty*8+i)*256 + klocal + qq*4]);
                            #pragma unroll
                            for (int ee=0;ee<4;ee++){
                                float4 bv = *reinterpret_cast<const float4*>(
                                                &W[(qq*4+ee)*256 + tx*4]);
                                #pragma unroll
                                for (int i=0;i<8;i++){
                                    float av = (ee==0)?a[i].x:(ee==1)?a[i].y:(ee==2)?a[i].z:a[i].w;
                                    acc4[i].x = fmaf(av, bv.x, acc4[i].x);
                                    acc4[i].y = fmaf(av, bv.y, acc4[i].y);
                                    acc4[i].z = fmaf(av, bv.z, acc4[i].z);
                                    acc4[i].w = fmaf(av, bv.w, acc4[i].w);
                                }
                            }
                        }
                    }
                    // store prefetched tile into other buffer
                    if (ktn < nkt){
                        float* W = WTb[bufc^1];
                        W[0*256+tid]=p0r.x; W[1*256+tid]=p0r.y; W[2*256+tid]=p0r.z; W[3*256+tid]=p0r.w;
                        W[4*256+tid]=p1r.x; W[5*256+tid]=p1r.y; W[6*256+tid]=p1r.z; W[7*256+tid]=p1r.w;
                    }
                    __syncthreads();
                    bufc ^= 1;
                }

                // epilogue: one unit per thread, 8 rows
                int u = chunk*64 + tx;
                float4 p4 = *reinterpret_cast<const float4*>(&pre[chunk*256 + tx*4]);
                #pragma unroll
                for (int i=0;i<8;i++){
                    int row = ty*8 + i;
                    float gi = acc4[i].x + p4.x;
                    float gf = acc4[i].y + p4.y;
                    float gg = acc4[i].z + p4.z;
                    float go = acc4[i].w + p4.w;
                    float cold = cs[row*256 + u];
                    float cn = sigf(gf)*cold + sigf(gi)*tanhfa(gg);
                    float hn = sigf(go)*tanhfa(cn);
                    cs[row*256 + u]   = cn;
                    hout[row*256 + u] = hn;
                }
            }
        }
        __syncthreads();
    }

    // ---- write pr = final state + noise into pf (l,b,u,512) ----
    float sq = sqrtf(q[0]*q[0]);
    float se = sqrtf(e[0]*e[0]);
    const float* h0f = Hb + 0;        // parity 0 after 16 steps
    const float* h1f = Hb + 2*8192;
    for (int idx = tid; idx < 8192; idx += 256){
        int row = idx >> 8, u = idx & 255; int p = p0 + row;
        size_t o0 = ((size_t)(0*BSC + b)*NHC + u)*NPARTC;
        size_t o1 = ((size_t)(1*BSC + b)*NHC + u)*NPARTC;
        int e0 = ((p*LSC + 0)*BSC + b)*NHC + u;
        int e1 = ((p*LSC + 1)*BSC + b)*NHC + u;
        pf[o0 + p]          = h0f[row*256+u] + sq*eps_h[e0];
        pf[o1 + p]          = h1f[row*256+u] + sq*eps_h[e1];
        pf[o0 + MIDP + p]   = C0[row*256+u]  + se*eps_c[e0];
        pf[o1 + MIDP + p]   = C1[row*256+u]  + se*eps_c[e1];
    }
}

// ---------------- obs + weight update; preW staged into out.wf ---------------
__global__ __launch_bounds__(512)
void k_stats1(const float* __restrict__ weights, const float* __restrict__ y,
              const float* __restrict__ r, const float* __restrict__ pf,
              const float* __restrict__ Wh, const float* __restrict__ bh,
              float* __restrict__ out){
    __shared__ __align__(16) float ws[NHC];
    __shared__ float red[512];
    int b = blockIdx.x; int tid = threadIdx.x;
    if (tid < NHC) ws[tid] = Wh[tid];
    __syncthreads();
    float Yv = bh[0];
    const float* base = pf + ((size_t)(BSC + b)*NHC)*NPARTC;   // l=1
    for (int u=0; u<NHC; u++) Yv = fmaf(ws[u], base[(size_t)u*NPARTC + tid], Yv);
    float w  = logf(weights[b*NPARTC + tid]);
    float wsum = bsum(red, tid, 512, w);
    float s1   = bsum(red, tid, 512, Yv*w);
    float Wmu  = s1 / wsum;
    float cen  = Yv - Wmu;
    float cov  = bsum(red, tid, 512, cen*cen) / (float)(NPARTC-1) + r[0]*r[0];
    float s    = cov + 1e-6f;
    float innov = y[b] - Yv*w/wsum;
    out[OFF_WF + b*NPARTC + tid] = w - 0.5f*logf(s) - 0.5f*innov*innov/s;   // preW
}

// ---- normalize preW across the BATCH axis (reference quirk), in place -------
__global__ __launch_bounds__(512)
void k_norm(float* __restrict__ out){
    int n = threadIdx.x;
    float v[BSC];
    float s = 0.0f;
    #pragma unroll
    for (int b=0;b<BSC;b++){ v[b] = out[OFF_WF + b*NPARTC + n]; s += expf(v[b]); }
    float ls = logf(s);
    #pragma unroll
    for (int b=0;b<BSC;b++) out[OFF_WF + b*NPARTC + n] = expf(v[b] - ls);   // neww
}

// ---------------- per-(batch,half) resample: bitonic argsort of 256 ----------
// reads neww from out.wf, overwrites its own segment with final wf
__global__ __launch_bounds__(256)
void k_resample(const float* __restrict__ gumbel, float* __restrict__ out){
    __shared__ __align__(16) float key[256];
    __shared__ __align__(16) int   idxs[256];
    __shared__ __align__(16) float red[256];
    int blk = blockIdx.x; int b = blk>>1; int half = blk&1; int tid = threadIdx.x;
    float wh = out[OFF_WF + b*NPARTC + half*MIDP + tid];
    float ss = bsum(red, tid, 256, wh*wh);
    int dof = (1.0f/ss < (float)NPARTC/4.0f) ? 1 : 0;
    float soft = 0.5f*wh + 0.5f/(float)MIDP;
    key[tid]  = -(logf(soft) + gumbel[(b*2 + half)*MIDP + tid]);
    idxs[tid] = tid;
    __syncthreads();
    for (int k=2;k<=256;k<<=1){
        for (int j=k>>1;j>0;j>>=1){
            int ixj = tid ^ j;
            if (ixj > tid){
                bool up = ((tid & k) == 0);
                float a = key[tid], bk = key[ixj];
                if ((a > bk) == up){
                    key[tid]=bk; key[ixj]=a;
                    int t0=idxs[tid]; idxs[tid]=idxs[ixj]; idxs[ixj]=t0;
                }
            }
            __syncthreads();
        }
    }
    g_idx[blk*MIDP + tid] = idxs[tid];
    float lw = logf(wh/soft);
    float mx = bmax(red, tid, 256, lw);
    float se = bsum(red, tid, 256, expf(lw-mx));
    float lse = mx + logf(se);
    float wr = expf(lw - lse);
    out[OFF_WF + b*NPARTC + half*MIDP + tid] = dof ? wr : wh;
    if (tid==0) g_do[blk] = dof;
}

// ---------------- in-place gather on pf (per (b,half) permutation) -----------
__global__ __launch_bounds__(256)
void k_gather(float* __restrict__ pf){
    __shared__ __align__(16) float seg[8][256];
    __shared__ int idx_s[256];
    int blk = blockIdx.x;            // b*2+half
    int chunk = blockIdx.y;          // 0..63 -> 8 (l,u) rows each
    int b = blk>>1; int half = blk&1; int tid = threadIdx.x;
    if (!g_do[blk]) return;
    idx_s[tid] = g_idx[blk*MIDP + tid];
    int row0 = chunk*8;
    #pragma unroll
    for (int i=0;i<8;i++){
        int rr = row0 + i;
        int l = rr >> 8, u = rr & 255;
        seg[i][tid] = pf[(((size_t)(l*BSC+b))*NHC + u)*NPARTC + half*MIDP + tid];
    }
    __syncthreads();
    #pragma unroll
    for (int i=0;i<8;i++){
        int rr = row0 + i;
        int l = rr >> 8, u = rr & 255;
        pf[(((size_t)(l*BSC+b))*NHC + u)*NPARTC + half*MIDP + tid] = seg[i][idx_s[tid]];
    }
}

// ---------------- final estimate (obs fused, 16 blocks) ----------------------
__global__ __launch_bounds__(512)
void k_stats2(const float* __restrict__ y, const float* __restrict__ r,
              const float* __restrict__ pf, const float* __restrict__ Wh,
              const float* __restrict__ bh, float* __restrict__ out){
    __shared__ __align__(16) float ws[NHC];
    __shared__ float red[512];
    int b = blockIdx.x; int tid = threadIdx.x;
    if (tid < NHC) ws[tid] = Wh[tid];
    __syncthreads();
    float Yv = bh[0];
    const float* base = pf + ((size_t)(BSC + b)*NHC)*NPARTC;   // l=1
    for (int u=0; u<NHC; u++) Yv = fmaf(ws[u], base[(size_t)u*NPARTC + tid], Yv);
    float wv = out[OFF_WF + b*NPARTC + tid];
    float wsum = bsum(red, tid, 512, wv);
    float Wmu  = bsum(red, tid, 512, Yv*wv) / wsum;
    float cen  = Yv - Wmu;
    float cov  = bsum(red, tid, 512, cen*cen) / (float)(NPARTC-1) + r[0]*r[0];
    if (tid==0){
        out[OFF_WMU + b] = Wmu;
        out[OFF_SIG + b] = cov;
    }
}

// ---- scalars recomputed from already-written W_mu/sig (no extra globals) ----
__global__ __launch_bounds__(32)
void k_scalars(const float* __restrict__ y, float* __restrict__ out){
    if (threadIdx.x != 0) return;
    float l = 0.0f, nq = 0.0f;
    for (int b=0;b<BSC;b++){
        float s = out[OFF_SIG + b] + 1e-6f;
        float inn = y[b] - out[OFF_WMU + b];
        float qf = inn*inn/s;
        l += -0.5f*logf(s) - 0.5f*qf;
        nq += qf;
    }
    out[OFF_L]   = l;
    out[OFF_NIS] = nq / (float)BSC;
}

// =============================================================================
extern "C" void kernel_launch(void* const* d_in, const int* in_sizes, int n_in,
                              void* d_out, int out_size){
    const float* x        = (const float*)d_in[0];
    const float* y        = (const float*)d_in[1];
    const float* particles= (const float*)d_in[2];
    const float* weights  = (const float*)d_in[3];
    const float* q        = (const float*)d_in[4];
    const float* e        = (const float*)d_in[5];
    const float* r        = (const float*)d_in[6];
    const float* Wih0     = (const float*)d_in[7];
    const float* Whh0     = (const float*)d_in[8];
    const float* b0       = (const float*)d_in[9];
    const float* Wih1     = (const float*)d_in[10];
    const float* Whh1     = (const float*)d_in[11];
    const float* b1       = (const float*)d_in[12];
    const float* Wh       = (const float*)d_in[13];
    const float* bh       = (const float*)d_in[14];
    const float* eps_h    = (const float*)d_in[15];
    const float* eps_c    = (const float*)d_in[16];
    const float* gumbel   = (const float*)d_in[17];
    float* out = (float*)d_out;
    float* pf  = out + OFF_PF;

    static bool attr_set = false;
    if (!attr_set){
        cudaFuncSetAttribute(k_lstm, cudaFuncAttributeMaxDynamicSharedMemorySize, SMEM_BYTES);
        attr_set = true;
    }

    // 1. full recurrence, state in shared; writes pr into pf
    k_lstm<<<128, 256, SMEM_BYTES>>>(x, particles, q, e,
                                     Wih0, Whh0, b0, Wih1, Whh1, b1,
                                     eps_h, eps_c, pf);
    // 2. obs + weight update (preW -> out.wf), batch-axis norm in place
    k_stats1<<<BSC, 512>>>(weights, y, r, pf, Wh, bh, out);
    k_norm<<<1, 512>>>(out);
    // 3. resample halves (reads neww from out.wf, writes final wf + g_idx/g_do)
    k_resample<<<BSC*2, 256>>>(gumbel, out);
    // 4. in-place gather pr -> pf
    k_gather<<<dim3(BSC*2, 64), 256>>>(pf);
    // 5. final obs + estimate, then scalars
    k_stats2<<<BSC, 512>>>(y, r, pf, Wh, bh, out);
    k_scalars<<<1, 32>>>(y, out);
}